// round 1
// baseline (speedup 1.0000x reference)
#include <cuda_runtime.h>
#include <math.h>

#define N2     4096
#define D      512
#define HALF_N 2048
#define BM     128
#define BN     128
#define BK     8
#define PAD    132          // BM + 4 -> conflict-free transpose stores, 16B-aligned rows (132*4=528=33*16)
#define NCOLT  (N2 / BN)    // 32 column tiles
#define NROWT  (N2 / BM)    // 32 row tiles

// Scratch (allocation-free rule: __device__ globals)
__device__ float g_xn[N2 * D];        // normalized rows, fp32 (8 MB)
__device__ float g_part[NCOLT * N2];  // per-(coltile,row) partial sum of exp(sim) (512 KB)
__device__ float g_pos[N2];           // positive logit per row

// ---------------------------------------------------------------------------
// Kernel 1: row L2 norms (clamped at 1e-8, torch CosineSimilarity eps), write xn
// ---------------------------------------------------------------------------
__global__ void __launch_bounds__(128) norm_kernel(const float* __restrict__ x) {
    int row = blockIdx.x;
    int t = threadIdx.x;                       // 128 threads, 1 float4 each (512 floats/row)
    const float4* xr = reinterpret_cast<const float4*>(x + (size_t)row * D);
    float4 v = xr[t];
    float ss = v.x * v.x + v.y * v.y + v.z * v.z + v.w * v.w;
    #pragma unroll
    for (int o = 16; o; o >>= 1) ss += __shfl_xor_sync(0xffffffffu, ss, o);
    __shared__ float ws[4];
    if ((t & 31) == 0) ws[t >> 5] = ss;
    __syncthreads();
    float tot = ws[0] + ws[1] + ws[2] + ws[3];
    float inv = 1.0f / fmaxf(sqrtf(tot), 1e-8f);
    float4 o4 = make_float4(v.x * inv, v.y * inv, v.z * inv, v.w * inv);
    reinterpret_cast<float4*>(g_xn + (size_t)row * D)[t] = o4;
}

// ---------------------------------------------------------------------------
// Kernel 2: fused GEMM (xn @ xn^T) + exp + row partial sums + positive logit
// 128x128 tile per CTA, 8x8 microtile per thread, BK=8, double-buffered smem.
// sim = 2 * dot (T = 0.5). Sum of exp over full row tile (diag handled later).
// ---------------------------------------------------------------------------
__global__ void __launch_bounds__(256, 2) simexp_kernel() {
    __shared__ float As[2][BK][PAD];
    __shared__ float Bs[2][BK][PAD];

    int tid = threadIdx.x;
    int tx = tid & 15;        // column group 0..15
    int ty = tid >> 4;        // row group 0..15
    int i0 = blockIdx.y * BM;
    int j0 = blockIdx.x * BN;

    int lrow = tid >> 1;            // 0..127: tile row loaded by this thread
    int lk4  = (tid & 1) * 4;       // 0 or 4: k offset of its float4

    const float* Aptr = g_xn + (size_t)(i0 + lrow) * D + lk4;
    const float* Bptr = g_xn + (size_t)(j0 + lrow) * D + lk4;

    float acc[8][8];
    #pragma unroll
    for (int r = 0; r < 8; r++)
        #pragma unroll
        for (int c = 0; c < 8; c++) acc[r][c] = 0.0f;

    // prologue: load k-chunk 0 into buffer 0
    float4 a_reg = *reinterpret_cast<const float4*>(Aptr);
    float4 b_reg = *reinterpret_cast<const float4*>(Bptr);
    As[0][lk4 + 0][lrow] = a_reg.x; As[0][lk4 + 1][lrow] = a_reg.y;
    As[0][lk4 + 2][lrow] = a_reg.z; As[0][lk4 + 3][lrow] = a_reg.w;
    Bs[0][lk4 + 0][lrow] = b_reg.x; Bs[0][lk4 + 1][lrow] = b_reg.y;
    Bs[0][lk4 + 2][lrow] = b_reg.z; Bs[0][lk4 + 3][lrow] = b_reg.w;
    __syncthreads();

    const int KT = D / BK;  // 64
    for (int kt = 0; kt < KT; kt++) {
        int cur = kt & 1;
        if (kt < KT - 1) {
            a_reg = *reinterpret_cast<const float4*>(Aptr + (kt + 1) * BK);
            b_reg = *reinterpret_cast<const float4*>(Bptr + (kt + 1) * BK);
        }
        #pragma unroll
        for (int k = 0; k < BK; k++) {
            float4 a0 = *reinterpret_cast<const float4*>(&As[cur][k][ty * 8]);
            float4 a1 = *reinterpret_cast<const float4*>(&As[cur][k][ty * 8 + 4]);
            float4 b0 = *reinterpret_cast<const float4*>(&Bs[cur][k][tx * 8]);
            float4 b1 = *reinterpret_cast<const float4*>(&Bs[cur][k][tx * 8 + 4]);
            float a[8] = {a0.x, a0.y, a0.z, a0.w, a1.x, a1.y, a1.z, a1.w};
            float b[8] = {b0.x, b0.y, b0.z, b0.w, b1.x, b1.y, b1.z, b1.w};
            #pragma unroll
            for (int r = 0; r < 8; r++)
                #pragma unroll
                for (int c = 0; c < 8; c++)
                    acc[r][c] = fmaf(a[r], b[c], acc[r][c]);
        }
        if (kt < KT - 1) {
            int nxt = cur ^ 1;
            As[nxt][lk4 + 0][lrow] = a_reg.x; As[nxt][lk4 + 1][lrow] = a_reg.y;
            As[nxt][lk4 + 2][lrow] = a_reg.z; As[nxt][lk4 + 3][lrow] = a_reg.w;
            Bs[nxt][lk4 + 0][lrow] = b_reg.x; Bs[nxt][lk4 + 1][lrow] = b_reg.y;
            Bs[nxt][lk4 + 2][lrow] = b_reg.z; Bs[nxt][lk4 + 3][lrow] = b_reg.w;
        }
        __syncthreads();
    }

    // --- epilogue ---
    // positive logit: row gi pairs with column (gi + N) mod 2N; unique owner thread.
    #pragma unroll
    for (int r = 0; r < 8; r++) {
        int gi = i0 + ty * 8 + r;
        int pj = (gi + HALF_N) & (N2 - 1);
        int cc = pj - (j0 + tx * 8);
        if (cc >= 0 && cc < 8) {
            #pragma unroll
            for (int c = 0; c < 8; c++)
                if (c == cc) g_pos[gi] = 2.0f * acc[r][c];
        }
    }

    // exp + per-thread row sums over its 8 columns
    float rowsum[8];
    #pragma unroll
    for (int r = 0; r < 8; r++) {
        float s = 0.0f;
        #pragma unroll
        for (int c = 0; c < 8; c++) s += __expf(2.0f * acc[r][c]);
        rowsum[r] = s;
    }
    // butterfly reduce across the 16 tx lanes (xor<16 stays within ty half-warp)
    #pragma unroll
    for (int off = 8; off; off >>= 1)
        #pragma unroll
        for (int r = 0; r < 8; r++)
            rowsum[r] += __shfl_xor_sync(0xffffffffu, rowsum[r], off);

    if (tx == 0) {
        #pragma unroll
        for (int r = 0; r < 8; r++)
            g_part[blockIdx.x * N2 + i0 + ty * 8 + r] = rowsum[r];
    }
}

// ---------------------------------------------------------------------------
// Kernel 3: per-row lse = log(sum_exp - e^2), loss = mean(lse - pos)
// ---------------------------------------------------------------------------
__global__ void __launch_bounds__(256) finalize_kernel(float* __restrict__ out) {
    const float E2 = 7.38905609893065f;   // exp(2) = exp(sim_ii)
    int t = threadIdx.x;
    double local = 0.0;
    for (int r = t; r < N2; r += 256) {
        float s = 0.0f;
        #pragma unroll
        for (int jt = 0; jt < NCOLT; jt++) s += g_part[jt * N2 + r];
        local += (double)(logf(s - E2) - g_pos[r]);
    }
    __shared__ double red[256];
    red[t] = local;
    __syncthreads();
    for (int o = 128; o; o >>= 1) {
        if (t < o) red[t] += red[t + o];
        __syncthreads();
    }
    if (t == 0) out[0] = (float)(red[0] / (double)N2);
}

// ---------------------------------------------------------------------------
extern "C" void kernel_launch(void* const* d_in, const int* in_sizes, int n_in,
                              void* d_out, int out_size) {
    const float* x = (const float*)d_in[0];
    float* out = (float*)d_out;

    norm_kernel<<<N2, 128>>>(x);
    dim3 grid(NCOLT, NROWT);
    simexp_kernel<<<grid, 256>>>();
    finalize_kernel<<<1, 256>>>(out);
}

// round 3
// speedup vs baseline: 3.5809x; 3.5809x over previous
#include <cuda_runtime.h>
#include <cuda_bf16.h>
#include <cstdint>
#include <math.h>

#define N2     4096
#define D      512
#define HALF_N 2048
#define NCOLT  32
#define NROWT  32
#define NPART  64            // partial slots per row: 32 col-tiles x 2 warp-cols
// sqrt(2*log2(e)): inputs pre-scaled so acc = 2*log2e*dot = log2(exp(sim))
#define ALPHA  1.69864360f

// Scratch (__device__ globals: allocation-free rule)
__device__ __nv_bfloat16 g_xb[N2 * D];     // normalized, alpha-scaled bf16 (4 MB)
__device__ float g_part[N2 * NPART];       // per-row partial sums of exp (1 MB)
__device__ float g_pos[N2];                // positive logit per row

__device__ __forceinline__ uint32_t smem_u32(const void* p) {
    uint32_t a;
    asm("{ .reg .u64 t; cvta.to.shared.u64 t, %1; cvt.u32.u64 %0, t; }" : "=r"(a) : "l"(p));
    return a;
}
__device__ __forceinline__ float ex2f(float x) {
    float y; asm("ex2.approx.f32 %0, %1;" : "=f"(y) : "f"(x)); return y;
}

#define CP16(sm, gm)  asm volatile("cp.async.cg.shared.global [%0], [%1], 16;" :: "r"(sm), "l"(gm) : "memory")
#define CP_COMMIT()   asm volatile("cp.async.commit_group;" ::: "memory")
#define CP_WAIT1()    asm volatile("cp.async.wait_group 1;" ::: "memory")
#define CP_WAIT0()    asm volatile("cp.async.wait_group 0;" ::: "memory")

#define LDSM_X4(r0, r1, r2, r3, addr)                                         \
    asm volatile("ldmatrix.sync.aligned.m8n8.x4.shared.b16 {%0,%1,%2,%3}, [%4];" \
        : "=r"(r0), "=r"(r1), "=r"(r2), "=r"(r3) : "r"(addr))

#define MMA16816(c, a, b0, b1)                                                \
    asm volatile("mma.sync.aligned.m16n8k16.row.col.f32.bf16.bf16.f32 "       \
        "{%0,%1,%2,%3}, {%4,%5,%6,%7}, {%8,%9}, {%0,%1,%2,%3};"               \
        : "+f"((c)[0]), "+f"((c)[1]), "+f"((c)[2]), "+f"((c)[3])              \
        : "r"((a)[0]), "r"((a)[1]), "r"((a)[2]), "r"((a)[3]), "r"(b0), "r"(b1))

// ---------------------------------------------------------------------------
// Kernel 1: row L2 norms (clamped at 1e-8), write bf16 xn * ALPHA
// ---------------------------------------------------------------------------
__global__ void __launch_bounds__(128) norm_kernel(const float* __restrict__ x) {
    int row = blockIdx.x;
    int t = threadIdx.x;
    float4 v = reinterpret_cast<const float4*>(x + (size_t)row * D)[t];
    float ss = v.x * v.x + v.y * v.y + v.z * v.z + v.w * v.w;
    #pragma unroll
    for (int o = 16; o; o >>= 1) ss += __shfl_xor_sync(0xffffffffu, ss, o);
    __shared__ float ws[4];
    if ((t & 31) == 0) ws[t >> 5] = ss;
    __syncthreads();
    float inv = ALPHA / fmaxf(sqrtf(ws[0] + ws[1] + ws[2] + ws[3]), 1e-8f);
    __nv_bfloat162* orow = reinterpret_cast<__nv_bfloat162*>(g_xb + (size_t)row * D);
    orow[2 * t]     = __floats2bfloat162_rn(v.x * inv, v.y * inv);
    orow[2 * t + 1] = __floats2bfloat162_rn(v.z * inv, v.w * inv);
}

// ---------------------------------------------------------------------------
// Kernel 2: bf16 HMMA GEMM tile (128x128) + exp + row partial sums + pos
// 256 thr, warps 4(m) x 2(n); warp tile 32x64; BK=64; 2-stage cp.async; SW128.
// ---------------------------------------------------------------------------
#define TILE_B     16384                        // 128 rows x 128 bytes per matrix stage
#define SMEM_TOTAL (1024 + 4 * TILE_B)

__global__ void __launch_bounds__(256, 2) simexp_mma_kernel() {
    extern __shared__ char smem_raw[];
    uint32_t tiles = (smem_u32(smem_raw) + 1023) & ~1023u;

    const int tid = threadIdx.x, wid = tid >> 5, lane = tid & 31;
    const int wr = wid & 3, wc = wid >> 2;
    const int i0 = blockIdx.y * 128, j0 = blockIdx.x * 128;

    // ldmatrix lane mapping: q = lane>>3 -> (row_in16, k-half)
    const int lr8   = lane & 7;
    const int rin16 = lr8 + ((lane >> 3) & 1) * 8;    // row within a 16-row frag
    const int hioff = ((lane >> 4) & 1) * 16;         // k-half byte offset
    const uint32_t rx = (uint32_t)lr8 << 4;           // SW128 xor for this row

    const uint32_t offA0 = (uint32_t)(wr * 32 + rin16) * 128;   // + mf*2048
    const uint32_t offB0 = (uint32_t)(wc * 64 + rin16) * 128;   // + p*2048

    // --- loader: thread t loads row t>>1, 64B half (t&1) of each matrix ---
    const int lrow = tid >> 1;
    const uint32_t lhalf = (uint32_t)(tid & 1) * 64;
    const uint32_t lrx = (uint32_t)(lrow & 7) << 4;
    const __nv_bfloat16* gA = g_xb + (size_t)(i0 + lrow) * D;
    const __nv_bfloat16* gB = g_xb + (size_t)(j0 + lrow) * D;

    auto load_chunk = [&](int c, int s) {
        uint32_t sA = tiles + (uint32_t)s * (2 * TILE_B);
        uint32_t sB = sA + TILE_B;
        const __nv_bfloat16* pa = gA + c * 64;
        const __nv_bfloat16* pb = gB + c * 64;
        #pragma unroll
        for (int i = 0; i < 4; i++) {
            uint32_t klo = lhalf + i * 16;
            uint32_t sw = (uint32_t)lrow * 128 + (klo ^ lrx);
            CP16(sA + sw, pa + (klo >> 1));
            CP16(sB + sw, pb + (klo >> 1));
        }
        CP_COMMIT();
    };

    float acc[2][8][4];
    #pragma unroll
    for (int mf = 0; mf < 2; mf++)
        #pragma unroll
        for (int nf = 0; nf < 8; nf++)
            #pragma unroll
            for (int e = 0; e < 4; e++) acc[mf][nf][e] = 0.0f;

    load_chunk(0, 0);
    load_chunk(1, 1);

    for (int c = 0; c < 8; c++) {
        int s = c & 1;
        if (c < 7) CP_WAIT1(); else CP_WAIT0();
        __syncthreads();

        uint32_t sA = tiles + (uint32_t)s * (2 * TILE_B);
        uint32_t sB = sA + TILE_B;

        #pragma unroll
        for (int ks = 0; ks < 4; ks++) {
            uint32_t kx = ((uint32_t)(ks * 32) + hioff) ^ rx;
            uint32_t a[2][4], b[4][4];
            #pragma unroll
            for (int mf = 0; mf < 2; mf++)
                LDSM_X4(a[mf][0], a[mf][1], a[mf][2], a[mf][3],
                        sA + offA0 + (uint32_t)mf * 2048 + kx);
            #pragma unroll
            for (int p = 0; p < 4; p++)
                LDSM_X4(b[p][0], b[p][1], b[p][2], b[p][3],
                        sB + offB0 + (uint32_t)p * 2048 + kx);
            #pragma unroll
            for (int mf = 0; mf < 2; mf++)
                #pragma unroll
                for (int nf = 0; nf < 8; nf++) {
                    int p = nf >> 1, h = nf & 1;
                    MMA16816(acc[mf][nf], a[mf], b[p][h], b[p][h + 2]);
                }
        }
        if (c < 6) {
            __syncthreads();
            load_chunk(c + 2, s);
        }
    }

    // --- epilogue: exp + row sums + positive logit (register accumulators) ---
    const float LN2 = 0.69314718056f;
    #pragma unroll
    for (int mf = 0; mf < 2; mf++) {
        #pragma unroll
        for (int h = 0; h < 2; h++) {
            int gi = i0 + wr * 32 + mf * 16 + (lane >> 2) + h * 8;
            int pj = (gi + HALF_N) & (N2 - 1);          // positive column (global)
            float rs = 0.0f;
            #pragma unroll
            for (int nf = 0; nf < 8; nf++) {
                float v0 = acc[mf][nf][2 * h];
                float v1 = acc[mf][nf][2 * h + 1];
                rs += ex2f(v0) + ex2f(v1);
                int cbase = j0 + wc * 64 + nf * 8 + (lane & 3) * 2;
                if (cbase == pj)     g_pos[gi] = v0 * LN2;
                if (cbase + 1 == pj) g_pos[gi] = v1 * LN2;
            }
            rs += __shfl_xor_sync(0xffffffffu, rs, 1);
            rs += __shfl_xor_sync(0xffffffffu, rs, 2);
            if ((lane & 3) == 0)
                g_part[(size_t)gi * NPART + blockIdx.x * 2 + wc] = rs;
        }
    }
}

// ---------------------------------------------------------------------------
// Kernel 3: per-row lse = log(sum_exp - e^2), loss = mean(lse - pos)
// ---------------------------------------------------------------------------
__global__ void __launch_bounds__(1024) finalize_kernel(float* __restrict__ out) {
    const float E2 = 7.38905609893065f;   // exp(sim_ii) = e^2
    int t = threadIdx.x;
    double local = 0.0;
    #pragma unroll
    for (int k = 0; k < 4; k++) {
        int r = t + k * 1024;
        const float4* pr = reinterpret_cast<const float4*>(g_part + (size_t)r * NPART);
        float s = 0.0f;
        #pragma unroll
        for (int i = 0; i < 16; i++) {
            float4 v = pr[i];
            s += (v.x + v.y) + (v.z + v.w);
        }
        local += (double)(logf(s - E2) - g_pos[r]);
    }
    __shared__ double red[1024];
    red[t] = local;
    __syncthreads();
    for (int o = 512; o; o >>= 1) {
        if (t < o) red[t] += red[t + o];
        __syncthreads();
    }
    if (t == 0) out[0] = (float)(red[0] / (double)N2);
}

// ---------------------------------------------------------------------------
extern "C" void kernel_launch(void* const* d_in, const int* in_sizes, int n_in,
                              void* d_out, int out_size) {
    const float* x = (const float*)d_in[0];
    float* out = (float*)d_out;

    cudaFuncSetAttribute(simexp_mma_kernel,
                         cudaFuncAttributeMaxDynamicSharedMemorySize, SMEM_TOTAL);

    norm_kernel<<<N2, 128>>>(x);
    simexp_mma_kernel<<<dim3(NCOLT, NROWT), 256, SMEM_TOTAL>>>();
    finalize_kernel<<<1, 1024>>>(out);
}

// round 4
// speedup vs baseline: 8.3891x; 2.3427x over previous
#include <cuda_runtime.h>
#include <cuda_bf16.h>
#include <cstdint>
#include <math.h>

#define N2     4096
#define D      512
#define HALF_N 2048
#define NTILE  32            // 4096/128 tiles per dim
#define NBLK   528           // upper-triangular tiles: 32*33/2
#define NPART  96            // slots/row: 64 direct (tj*2+wc) + 32 transposed (ti)
// sqrt(2*log2(e)): inputs pre-scaled so acc = 2*log2e*dot = log2(exp(sim))
#define ALPHA  1.69864360f

__device__ __nv_bfloat16 g_xb[N2 * D];   // normalized, alpha-scaled bf16 (4 MB)
__device__ float g_part[N2 * NPART];     // partial sums of exp (zero-init; unwritten slots stay 0)
__device__ float g_pos[N2];              // positive logit per row
__device__ float g_lse[N2];              // per-row loss term

__device__ __forceinline__ uint32_t smem_u32(const void* p) {
    uint32_t a;
    asm("{ .reg .u64 t; cvta.to.shared.u64 t, %1; cvt.u32.u64 %0, t; }" : "=r"(a) : "l"(p));
    return a;
}
__device__ __forceinline__ float ex2f(float x) {
    float y; asm("ex2.approx.f32 %0, %1;" : "=f"(y) : "f"(x)); return y;
}

#define CP16(sm, gm)  asm volatile("cp.async.cg.shared.global [%0], [%1], 16;" :: "r"(sm), "l"(gm) : "memory")
#define CP_COMMIT()   asm volatile("cp.async.commit_group;" ::: "memory")
#define CP_WAIT1()    asm volatile("cp.async.wait_group 1;" ::: "memory")
#define CP_WAIT0()    asm volatile("cp.async.wait_group 0;" ::: "memory")

#define LDSM_X4(r0, r1, r2, r3, addr)                                         \
    asm volatile("ldmatrix.sync.aligned.m8n8.x4.shared.b16 {%0,%1,%2,%3}, [%4];" \
        : "=r"(r0), "=r"(r1), "=r"(r2), "=r"(r3) : "r"(addr))

#define MMA16816(c, a, b0, b1)                                                \
    asm volatile("mma.sync.aligned.m16n8k16.row.col.f32.bf16.bf16.f32 "       \
        "{%0,%1,%2,%3}, {%4,%5,%6,%7}, {%8,%9}, {%0,%1,%2,%3};"               \
        : "+f"((c)[0]), "+f"((c)[1]), "+f"((c)[2]), "+f"((c)[3])              \
        : "r"((a)[0]), "r"((a)[1]), "r"((a)[2]), "r"((a)[3]), "r"(b0), "r"(b1))

// ---------------------------------------------------------------------------
// Kernel 1: warp-per-row L2 norm (clamp 1e-8), write bf16 xn * ALPHA
// ---------------------------------------------------------------------------
__global__ void __launch_bounds__(256) norm_kernel(const float* __restrict__ x) {
    int warp = threadIdx.x >> 5, lane = threadIdx.x & 31;
    int row = blockIdx.x * 8 + warp;
    const float4* xr = reinterpret_cast<const float4*>(x + (size_t)row * D);
    float4 v[4];
    float ss = 0.0f;
    #pragma unroll
    for (int i = 0; i < 4; i++) {
        v[i] = xr[lane + 32 * i];
        ss += v[i].x * v[i].x + v[i].y * v[i].y + v[i].z * v[i].z + v[i].w * v[i].w;
    }
    #pragma unroll
    for (int o = 16; o; o >>= 1) ss += __shfl_xor_sync(0xffffffffu, ss, o);
    float inv = ALPHA / fmaxf(sqrtf(ss), 1e-8f);
    __nv_bfloat162* orow = reinterpret_cast<__nv_bfloat162*>(g_xb + (size_t)row * D);
    #pragma unroll
    for (int i = 0; i < 4; i++) {
        orow[2 * (lane + 32 * i)]     = __floats2bfloat162_rn(v[i].x * inv, v[i].y * inv);
        orow[2 * (lane + 32 * i) + 1] = __floats2bfloat162_rn(v[i].z * inv, v[i].w * inv);
    }
}

// ---------------------------------------------------------------------------
// Kernel 2: upper-triangle bf16 HMMA tiles + exp + row/col partials + pos
// 256 thr, warps 4(m)x2(n), warp tile 32x64, BK=64, 3-stage cp.async, SW128.
// ---------------------------------------------------------------------------
#define TILE_B     16384          // 128 rows x 128B (one matrix, one stage)
#define STAGE_B    32768          // A+B per stage
#define SMEM_TOTAL (1024 + 3 * STAGE_B)

__global__ void __launch_bounds__(256, 2) simexp_mma_kernel() {
    extern __shared__ char smem_raw[];
    uint32_t tiles = (smem_u32(smem_raw) + 1023) & ~1023u;

    const int tid = threadIdx.x, wid = tid >> 5, lane = tid & 31;
    const int wr = wid & 3, wc = wid >> 2;

    // decode upper-triangular tile (ti, tj), ti <= tj
    int b = blockIdx.x, ti = 0;
    while (b >= NTILE - ti) { b -= NTILE - ti; ti++; }
    const int tj = ti + b;
    const int i0 = ti * 128, j0 = tj * 128;
    const bool diag = (ti == tj);
    const uint32_t sBoff = diag ? 0u : (uint32_t)TILE_B;

    // ldmatrix lane mapping
    const int lr8   = lane & 7;
    const int rin16 = lr8 + ((lane >> 3) & 1) * 8;
    const int hioff = ((lane >> 4) & 1) * 16;
    const uint32_t rx = (uint32_t)lr8 << 4;
    const uint32_t offA0 = (uint32_t)(wr * 32 + rin16) * 128;
    const uint32_t offB0 = (uint32_t)(wc * 64 + rin16) * 128;

    // loader: thread covers 4 rows (rb + 32p), 16B at byte-col klo
    const int rb = tid >> 3;
    const int klo = (tid & 7) * 16;
    uint32_t swo[4];
    const __nv_bfloat16 *pA[4], *pB[4];
    #pragma unroll
    for (int p = 0; p < 4; p++) {
        int row = rb + 32 * p;
        swo[p] = (uint32_t)row * 128 + ((uint32_t)klo ^ ((uint32_t)(row & 7) << 4));
        pA[p] = g_xb + (size_t)(i0 + row) * D + (klo >> 1);
        pB[p] = g_xb + (size_t)(j0 + row) * D + (klo >> 1);
    }
    auto load_chunk = [&](int c, int s) {
        uint32_t bA = tiles + (uint32_t)s * STAGE_B;
        #pragma unroll
        for (int p = 0; p < 4; p++) CP16(bA + swo[p], pA[p] + c * 64);
        if (!diag) {
            uint32_t bB = bA + TILE_B;
            #pragma unroll
            for (int p = 0; p < 4; p++) CP16(bB + swo[p], pB[p] + c * 64);
        }
        CP_COMMIT();
    };

    float acc[2][8][4];
    #pragma unroll
    for (int mf = 0; mf < 2; mf++)
        #pragma unroll
        for (int nf = 0; nf < 8; nf++)
            #pragma unroll
            for (int e = 0; e < 4; e++) acc[mf][nf][e] = 0.0f;

    load_chunk(0, 0);
    load_chunk(1, 1);

    for (int c = 0; c < 8; c++) {
        if (c < 7) CP_WAIT1(); else CP_WAIT0();
        __syncthreads();
        if (c + 2 < 8) load_chunk(c + 2, (c + 2) % 3);

        uint32_t sA = tiles + (uint32_t)(c % 3) * STAGE_B;
        uint32_t sB = sA + sBoff;
        #pragma unroll
        for (int ks = 0; ks < 4; ks++) {
            uint32_t kx = ((uint32_t)(ks * 32) + hioff) ^ rx;
            uint32_t a[2][4], bb[4][4];
            #pragma unroll
            for (int mf = 0; mf < 2; mf++)
                LDSM_X4(a[mf][0], a[mf][1], a[mf][2], a[mf][3],
                        sA + offA0 + (uint32_t)mf * 2048 + kx);
            #pragma unroll
            for (int p = 0; p < 4; p++)
                LDSM_X4(bb[p][0], bb[p][1], bb[p][2], bb[p][3],
                        sB + offB0 + (uint32_t)p * 2048 + kx);
            #pragma unroll
            for (int mf = 0; mf < 2; mf++)
                #pragma unroll
                for (int nf = 0; nf < 8; nf++) {
                    int p = nf >> 1, h = nf & 1;
                    MMA16816(acc[mf][nf], a[mf], bb[p][h], bb[p][h + 2]);
                }
        }
    }
    __syncthreads();   // smem now free for col-sum reduction

    const float LN2 = 0.69314718056f;

    // positive logit: tiles with tj-ti == 16 hold (i, i+2048) at local (r, r)
    if (tj - ti == 16) {
        #pragma unroll
        for (int mf = 0; mf < 2; mf++)
            #pragma unroll
            for (int h = 0; h < 2; h++) {
                int gi = i0 + wr * 32 + mf * 16 + (lane >> 2) + h * 8;
                int pj = gi + HALF_N;           // global positive column, in this tile
                #pragma unroll
                for (int nf = 0; nf < 8; nf++) {
                    int cb = j0 + wc * 64 + nf * 8 + (lane & 3) * 2;
                    if (cb == pj) {
                        float v = acc[mf][nf][2 * h] * LN2;
                        g_pos[gi] = v; g_pos[pj & (N2 - 1)] = v;
                    }
                    if (cb + 1 == pj) {
                        float v = acc[mf][nf][2 * h + 1] * LN2;
                        g_pos[gi] = v; g_pos[pj & (N2 - 1)] = v;
                    }
                }
            }
    }

    // exp in place
    #pragma unroll
    for (int mf = 0; mf < 2; mf++)
        #pragma unroll
        for (int nf = 0; nf < 8; nf++)
            #pragma unroll
            for (int e = 0; e < 4; e++) acc[mf][nf][e] = ex2f(acc[mf][nf][e]);

    // row sums -> direct slots
    #pragma unroll
    for (int mf = 0; mf < 2; mf++)
        #pragma unroll
        for (int h = 0; h < 2; h++) {
            float rs = 0.0f;
            #pragma unroll
            for (int nf = 0; nf < 8; nf++)
                rs += acc[mf][nf][2 * h] + acc[mf][nf][2 * h + 1];
            rs += __shfl_xor_sync(0xffffffffu, rs, 1);
            rs += __shfl_xor_sync(0xffffffffu, rs, 2);
            if ((lane & 3) == 0) {
                int gi = i0 + wr * 32 + mf * 16 + (lane >> 2) + h * 8;
                g_part[(size_t)gi * NPART + tj * 2 + wc] = rs;
            }
        }

    // col sums -> transposed slots (off-diagonal tiles only)
    if (!diag) {
        float* cs_smem = reinterpret_cast<float*>(smem_raw) +
                         ((tiles - smem_u32(smem_raw)) >> 2);
        float cs[8][2];
        #pragma unroll
        for (int nf = 0; nf < 8; nf++) {
            cs[nf][0] = acc[0][nf][0] + acc[0][nf][2] + acc[1][nf][0] + acc[1][nf][2];
            cs[nf][1] = acc[0][nf][1] + acc[0][nf][3] + acc[1][nf][1] + acc[1][nf][3];
            #pragma unroll
            for (int o = 4; o <= 16; o <<= 1) {
                cs[nf][0] += __shfl_xor_sync(0xffffffffu, cs[nf][0], o);
                cs[nf][1] += __shfl_xor_sync(0xffffffffu, cs[nf][1], o);
            }
        }
        if (lane < 4) {
            #pragma unroll
            for (int nf = 0; nf < 8; nf++) {
                cs_smem[wr * 128 + wc * 64 + nf * 8 + lane * 2]     = cs[nf][0];
                cs_smem[wr * 128 + wc * 64 + nf * 8 + lane * 2 + 1] = cs[nf][1];
            }
        }
        __syncthreads();
        if (tid < 128) {
            float t = cs_smem[tid] + cs_smem[128 + tid] +
                      cs_smem[256 + tid] + cs_smem[384 + tid];
            g_part[(size_t)(j0 + tid) * NPART + 64 + ti] = t;
        }
    }
}

// ---------------------------------------------------------------------------
// Kernel 3a: per-row lse - pos  (parallel over rows)
// ---------------------------------------------------------------------------
__global__ void __launch_bounds__(256) finalizeA_kernel() {
    const float E2 = 7.38905609893065f;
    int r = blockIdx.x * 256 + threadIdx.x;
    const float4* pr = reinterpret_cast<const float4*>(g_part + (size_t)r * NPART);
    float s = 0.0f;
    #pragma unroll
    for (int i = 0; i < NPART / 4; i++) {
        float4 v = pr[i];
        s += (v.x + v.y) + (v.z + v.w);
    }
    g_lse[r] = logf(s - E2) - g_pos[r];
}

// ---------------------------------------------------------------------------
// Kernel 3b: mean over 4096 rows
// ---------------------------------------------------------------------------
__global__ void __launch_bounds__(1024) finalizeB_kernel(float* __restrict__ out) {
    int t = threadIdx.x;
    double local = 0.0;
    #pragma unroll
    for (int k = 0; k < 4; k++) local += (double)g_lse[t + k * 1024];
    __shared__ double red[1024];
    red[t] = local;
    __syncthreads();
    for (int o = 512; o; o >>= 1) {
        if (t < o) red[t] += red[t + o];
        __syncthreads();
    }
    if (t == 0) out[0] = (float)(red[0] / (double)N2);
}

// ---------------------------------------------------------------------------
extern "C" void kernel_launch(void* const* d_in, const int* in_sizes, int n_in,
                              void* d_out, int out_size) {
    const float* x = (const float*)d_in[0];
    float* out = (float*)d_out;

    cudaFuncSetAttribute(simexp_mma_kernel,
                         cudaFuncAttributeMaxDynamicSharedMemorySize, SMEM_TOTAL);

    norm_kernel<<<N2 / 8, 256>>>(x);
    simexp_mma_kernel<<<NBLK, 256, SMEM_TOTAL>>>();
    finalizeA_kernel<<<N2 / 256, 256>>>();
    finalizeB_kernel<<<1, 1024>>>(out);
}

// round 5
// speedup vs baseline: 9.0522x; 1.0790x over previous
#include <cuda_runtime.h>
#include <cuda_bf16.h>
#include <cstdint>
#include <math.h>

#define N2     4096
#define D      512
#define HALF_N 2048
#define NTILE  32            // 4096/128 tiles per dim
#define NBLK   528           // upper-triangular tiles: 32*33/2
#define NPART  96            // slots/row: 64 direct (tj*2+wc) + 32 transposed (ti)
// sqrt(2*log2(e)): inputs pre-scaled so acc = 2*log2e*dot = log2(exp(sim))
#define ALPHA  1.69864360f

__device__ __nv_bfloat16 g_xb[N2 * D];   // normalized, alpha-scaled bf16 (4 MB)
__device__ float g_part[N2 * NPART];     // partial sums of exp (zero-init; unwritten slots stay 0)
__device__ float g_pos[N2];              // positive logit per row
__device__ double g_blk[16];             // per-block loss partials

__device__ __forceinline__ uint32_t smem_u32(const void* p) {
    uint32_t a;
    asm("{ .reg .u64 t; cvta.to.shared.u64 t, %1; cvt.u32.u64 %0, t; }" : "=r"(a) : "l"(p));
    return a;
}
__device__ __forceinline__ float ex2f(float x) {
    float y; asm("ex2.approx.f32 %0, %1;" : "=f"(y) : "f"(x)); return y;
}

#define CP16(sm, gm)  asm volatile("cp.async.cg.shared.global [%0], [%1], 16;" :: "r"(sm), "l"(gm) : "memory")
#define CP_COMMIT()   asm volatile("cp.async.commit_group;" ::: "memory")
#define CP_WAIT1()    asm volatile("cp.async.wait_group 1;" ::: "memory")
#define CP_WAIT0()    asm volatile("cp.async.wait_group 0;" ::: "memory")

#define LDSM_X4(r0, r1, r2, r3, addr)                                         \
    asm volatile("ldmatrix.sync.aligned.m8n8.x4.shared.b16 {%0,%1,%2,%3}, [%4];" \
        : "=r"(r0), "=r"(r1), "=r"(r2), "=r"(r3) : "r"(addr))

#define MMA16816(c, a, b0, b1)                                                \
    asm volatile("mma.sync.aligned.m16n8k16.row.col.f32.bf16.bf16.f32 "       \
        "{%0,%1,%2,%3}, {%4,%5,%6,%7}, {%8,%9}, {%0,%1,%2,%3};"               \
        : "+f"((c)[0]), "+f"((c)[1]), "+f"((c)[2]), "+f"((c)[3])              \
        : "r"((a)[0]), "r"((a)[1]), "r"((a)[2]), "r"((a)[3]), "r"(b0), "r"(b1))

// ---------------------------------------------------------------------------
// Kernel 1: warp-per-row L2 norm (clamp 1e-8), write bf16 xn * ALPHA
// ---------------------------------------------------------------------------
__global__ void __launch_bounds__(256) norm_kernel(const float* __restrict__ x) {
    int warp = threadIdx.x >> 5, lane = threadIdx.x & 31;
    int row = blockIdx.x * 8 + warp;
    const float4* xr = reinterpret_cast<const float4*>(x + (size_t)row * D);
    float4 v[4];
    float ss = 0.0f;
    #pragma unroll
    for (int i = 0; i < 4; i++) {
        v[i] = xr[lane + 32 * i];
        ss += v[i].x * v[i].x + v[i].y * v[i].y + v[i].z * v[i].z + v[i].w * v[i].w;
    }
    #pragma unroll
    for (int o = 16; o; o >>= 1) ss += __shfl_xor_sync(0xffffffffu, ss, o);
    float inv = ALPHA / fmaxf(sqrtf(ss), 1e-8f);
    __nv_bfloat162* orow = reinterpret_cast<__nv_bfloat162*>(g_xb + (size_t)row * D);
    #pragma unroll
    for (int i = 0; i < 4; i++) {
        orow[2 * (lane + 32 * i)]     = __floats2bfloat162_rn(v[i].x * inv, v[i].y * inv);
        orow[2 * (lane + 32 * i) + 1] = __floats2bfloat162_rn(v[i].z * inv, v[i].w * inv);
    }
}

// ---------------------------------------------------------------------------
// Kernel 2: persistent 2-tiles/CTA upper-triangle bf16 HMMA + fused epilogue
// 256 thr, warps 4(m)x2(n), warp tile 32x64, BK=64, 3-stage cp.async, SW128.
// Grid = 264 CTAs = exactly one residency wave (2 CTAs/SM), zero tail.
// ---------------------------------------------------------------------------
#define TILE_B     16384          // 128 rows x 128B (one matrix, one stage)
#define STAGE_B    32768          // A+B per stage
#define SMEM_TOTAL (1024 + 3 * STAGE_B)

__global__ void __launch_bounds__(256, 2) simexp_mma_kernel() {
    extern __shared__ char smem_raw[];
    uint32_t tiles = (smem_u32(smem_raw) + 1023) & ~1023u;
    float* cs_smem = reinterpret_cast<float*>(smem_raw) +
                     ((tiles - smem_u32(smem_raw)) >> 2);

    const int tid = threadIdx.x, wid = tid >> 5, lane = tid & 31;
    const int wr = wid & 3, wc = wid >> 2;

    // ldmatrix lane mapping (tile-independent)
    const int lr8   = lane & 7;
    const int rin16 = lr8 + ((lane >> 3) & 1) * 8;
    const int hioff = ((lane >> 4) & 1) * 16;
    const uint32_t rx = (uint32_t)lr8 << 4;
    const uint32_t offA0 = (uint32_t)(wr * 32 + rin16) * 128;
    const uint32_t offB0 = (uint32_t)(wc * 64 + rin16) * 128;

    // loader geometry (tile-independent): thread covers rows rb+32p, 16B col klo
    const int rb = tid >> 3;
    const int klo = (tid & 7) * 16;
    uint32_t swo[4];
    #pragma unroll
    for (int p = 0; p < 4; p++) {
        int row = rb + 32 * p;
        swo[p] = (uint32_t)row * 128 + ((uint32_t)klo ^ ((uint32_t)(row & 7) << 4));
    }

    #pragma unroll 1
    for (int half = 0; half < 2; half++) {
        // decode upper-triangular tile (ti, tj), ti <= tj
        int b = blockIdx.x * 2 + half, ti = 0;
        while (b >= NTILE - ti) { b -= NTILE - ti; ti++; }
        const int tj = ti + b;
        const int i0 = ti * 128, j0 = tj * 128;
        const bool diag = (ti == tj);
        const uint32_t sBoff = diag ? 0u : (uint32_t)TILE_B;

        const __nv_bfloat16 *pA[4], *pB[4];
        #pragma unroll
        for (int p = 0; p < 4; p++) {
            int row = rb + 32 * p;
            pA[p] = g_xb + (size_t)(i0 + row) * D + (klo >> 1);
            pB[p] = g_xb + (size_t)(j0 + row) * D + (klo >> 1);
        }
        auto load_chunk = [&](int c, int s) {
            uint32_t bA = tiles + (uint32_t)s * STAGE_B;
            #pragma unroll
            for (int p = 0; p < 4; p++) CP16(bA + swo[p], pA[p] + c * 64);
            if (!diag) {
                uint32_t bB = bA + TILE_B;
                #pragma unroll
                for (int p = 0; p < 4; p++) CP16(bB + swo[p], pB[p] + c * 64);
            }
            CP_COMMIT();
        };

        float acc[2][8][4];
        #pragma unroll
        for (int mf = 0; mf < 2; mf++)
            #pragma unroll
            for (int nf = 0; nf < 8; nf++)
                #pragma unroll
                for (int e = 0; e < 4; e++) acc[mf][nf][e] = 0.0f;

        load_chunk(0, 0);
        load_chunk(1, 1);

        for (int c = 0; c < 8; c++) {
            if (c < 7) CP_WAIT1(); else CP_WAIT0();
            __syncthreads();
            if (c + 2 < 8) load_chunk(c + 2, (c + 2) % 3);

            uint32_t sA = tiles + (uint32_t)(c % 3) * STAGE_B;
            uint32_t sB = sA + sBoff;
            #pragma unroll
            for (int ks = 0; ks < 4; ks++) {
                uint32_t kx = ((uint32_t)(ks * 32) + hioff) ^ rx;
                uint32_t a[2][4], bb[4][4];
                #pragma unroll
                for (int mf = 0; mf < 2; mf++)
                    LDSM_X4(a[mf][0], a[mf][1], a[mf][2], a[mf][3],
                            sA + offA0 + (uint32_t)mf * 2048 + kx);
                #pragma unroll
                for (int p = 0; p < 4; p++)
                    LDSM_X4(bb[p][0], bb[p][1], bb[p][2], bb[p][3],
                            sB + offB0 + (uint32_t)p * 2048 + kx);
                #pragma unroll
                for (int mf = 0; mf < 2; mf++)
                    #pragma unroll
                    for (int nf = 0; nf < 8; nf++) {
                        int p = nf >> 1, h = nf & 1;
                        MMA16816(acc[mf][nf], a[mf], bb[p][h], bb[p][h + 2]);
                    }
            }
        }
        __syncthreads();   // mainloop smem dead; cs_smem reuse safe

        const float LN2 = 0.69314718056f;

        // positive logit: tiles with tj-ti == 16 hold (i, i+2048) at local (r, r)
        if (tj - ti == 16) {
            #pragma unroll
            for (int mf = 0; mf < 2; mf++)
                #pragma unroll
                for (int h = 0; h < 2; h++) {
                    int gi = i0 + wr * 32 + mf * 16 + (lane >> 2) + h * 8;
                    int pj = gi + HALF_N;
                    #pragma unroll
                    for (int nf = 0; nf < 8; nf++) {
                        int cb = j0 + wc * 64 + nf * 8 + (lane & 3) * 2;
                        if (cb == pj) {
                            float v = acc[mf][nf][2 * h] * LN2;
                            g_pos[gi] = v; g_pos[pj & (N2 - 1)] = v;
                        }
                        if (cb + 1 == pj) {
                            float v = acc[mf][nf][2 * h + 1] * LN2;
                            g_pos[gi] = v; g_pos[pj & (N2 - 1)] = v;
                        }
                    }
                }
        }

        // exp in place
        #pragma unroll
        for (int mf = 0; mf < 2; mf++)
            #pragma unroll
            for (int nf = 0; nf < 8; nf++)
                #pragma unroll
                for (int e = 0; e < 4; e++) acc[mf][nf][e] = ex2f(acc[mf][nf][e]);

        // row sums -> direct slots
        #pragma unroll
        for (int mf = 0; mf < 2; mf++)
            #pragma unroll
            for (int h = 0; h < 2; h++) {
                float rs = 0.0f;
                #pragma unroll
                for (int nf = 0; nf < 8; nf++)
                    rs += acc[mf][nf][2 * h] + acc[mf][nf][2 * h + 1];
                rs += __shfl_xor_sync(0xffffffffu, rs, 1);
                rs += __shfl_xor_sync(0xffffffffu, rs, 2);
                if ((lane & 3) == 0) {
                    int gi = i0 + wr * 32 + mf * 16 + (lane >> 2) + h * 8;
                    g_part[(size_t)gi * NPART + tj * 2 + wc] = rs;
                }
            }

        // col sums -> transposed slots (off-diagonal tiles only)
        if (!diag) {
            float cs[8][2];
            #pragma unroll
            for (int nf = 0; nf < 8; nf++) {
                cs[nf][0] = acc[0][nf][0] + acc[0][nf][2] + acc[1][nf][0] + acc[1][nf][2];
                cs[nf][1] = acc[0][nf][1] + acc[0][nf][3] + acc[1][nf][1] + acc[1][nf][3];
                #pragma unroll
                for (int o = 4; o <= 16; o <<= 1) {
                    cs[nf][0] += __shfl_xor_sync(0xffffffffu, cs[nf][0], o);
                    cs[nf][1] += __shfl_xor_sync(0xffffffffu, cs[nf][1], o);
                }
            }
            if (lane < 4) {
                #pragma unroll
                for (int nf = 0; nf < 8; nf++) {
                    cs_smem[wr * 128 + wc * 64 + nf * 8 + lane * 2]     = cs[nf][0];
                    cs_smem[wr * 128 + wc * 64 + nf * 8 + lane * 2 + 1] = cs[nf][1];
                }
            }
            __syncthreads();
            if (tid < 128) {
                float t = cs_smem[tid] + cs_smem[128 + tid] +
                          cs_smem[256 + tid] + cs_smem[384 + tid];
                g_part[(size_t)(j0 + tid) * NPART + 64 + ti] = t;
            }
        }
        __syncthreads();   // protect cs_smem/stages before next tile's loads
    }
}

// ---------------------------------------------------------------------------
// Kernel 3a: per-row lse - pos, block-reduced to 16 double partials
// ---------------------------------------------------------------------------
__global__ void __launch_bounds__(256) finalizeA_kernel() {
    const float E2 = 7.38905609893065f;
    int r = blockIdx.x * 256 + threadIdx.x;
    const float4* pr = reinterpret_cast<const float4*>(g_part + (size_t)r * NPART);
    float s = 0.0f;
    #pragma unroll
    for (int i = 0; i < NPART / 4; i++) {
        float4 v = pr[i];
        s += (v.x + v.y) + (v.z + v.w);
    }
    double d = (double)(logf(s - E2) - g_pos[r]);
    #pragma unroll
    for (int o = 16; o; o >>= 1) d += __shfl_xor_sync(0xffffffffu, d, o);
    __shared__ double ws[8];
    if ((threadIdx.x & 31) == 0) ws[threadIdx.x >> 5] = d;
    __syncthreads();
    if (threadIdx.x < 8) {
        double t = ws[threadIdx.x];
        #pragma unroll
        for (int o = 4; o; o >>= 1) t += __shfl_xor_sync(0xffu, t, o);
        if (threadIdx.x == 0) g_blk[blockIdx.x] = t;
    }
}

// ---------------------------------------------------------------------------
// Kernel 3b: sum 16 partials -> mean
// ---------------------------------------------------------------------------
__global__ void __launch_bounds__(32) finalizeB_kernel(float* __restrict__ out) {
    int t = threadIdx.x;
    double d = (t < 16) ? g_blk[t] : 0.0;
    #pragma unroll
    for (int o = 16; o; o >>= 1) d += __shfl_xor_sync(0xffffffffu, d, o);
    if (t == 0) out[0] = (float)(d / (double)N2);
}

// ---------------------------------------------------------------------------
extern "C" void kernel_launch(void* const* d_in, const int* in_sizes, int n_in,
                              void* d_out, int out_size) {
    const float* x = (const float*)d_in[0];
    float* out = (float*)d_out;

    cudaFuncSetAttribute(simexp_mma_kernel,
                         cudaFuncAttributeMaxDynamicSharedMemorySize, SMEM_TOTAL);

    norm_kernel<<<N2 / 8, 256>>>(x);
    simexp_mma_kernel<<<NBLK / 2, 256, SMEM_TOTAL>>>();
    finalizeA_kernel<<<16, 256>>>();
    finalizeB_kernel<<<1, 32>>>(out);
}

// round 6
// speedup vs baseline: 9.5729x; 1.0575x over previous
#include <cuda_runtime.h>
#include <cuda_bf16.h>
#include <cuda_fp8.h>
#include <cstdint>
#include <math.h>

#define N2     4096
#define D      512
#define HALF_N 2048
#define NTILE  32            // 4096/128 tiles per dim
#define NBLK   528           // upper-triangular tiles: 32*33/2
#define NPART  96            // slots/row: 64 direct (tj*2+wc) + 32 transposed (ti)
// sqrt(2*log2(e)): acc(unscaled) = 2*log2e*dot = log2(exp(sim)); fp8 adds x32 per side
#define ALPHA  1.69864360f
#define QS     32.0f
#define SCI    (1.0f / 1024.0f)            // 1/(QS*QS)
#define LN2S   (0.69314718056f / 1024.0f)

__device__ uint8_t g_xq[N2 * D];         // normalized, alpha*32-scaled e4m3 (2 MB)
__device__ float g_part[N2 * NPART];     // partial sums of exp (zero-init; unwritten slots stay 0)
__device__ float g_pos[N2];              // positive logit per row
__device__ double g_blk[16];             // per-block loss partials
__device__ int g_cnt;                    // finalize completion counter (self-resetting)

__device__ __forceinline__ uint32_t smem_u32(const void* p) {
    uint32_t a;
    asm("{ .reg .u64 t; cvta.to.shared.u64 t, %1; cvt.u32.u64 %0, t; }" : "=r"(a) : "l"(p));
    return a;
}
__device__ __forceinline__ float ex2f(float x) {
    float y; asm("ex2.approx.f32 %0, %1;" : "=f"(y) : "f"(x)); return y;
}

#define CP16(sm, gm)  asm volatile("cp.async.cg.shared.global [%0], [%1], 16;" :: "r"(sm), "l"(gm) : "memory")
#define CP_COMMIT()   asm volatile("cp.async.commit_group;" ::: "memory")
#define CP_WAIT1()    asm volatile("cp.async.wait_group 1;" ::: "memory")
#define CP_WAIT0()    asm volatile("cp.async.wait_group 0;" ::: "memory")

#define LDSM_X4(r0, r1, r2, r3, addr)                                         \
    asm volatile("ldmatrix.sync.aligned.m8n8.x4.shared.b16 {%0,%1,%2,%3}, [%4];" \
        : "=r"(r0), "=r"(r1), "=r"(r2), "=r"(r3) : "r"(addr))

// m16n8k32 e4m3: fragment byte-layout identical to m16n8k16 bf16
#define MMAFP8(c, a, b0, b1)                                                  \
    asm volatile("mma.sync.aligned.m16n8k32.row.col.f32.e4m3.e4m3.f32 "       \
        "{%0,%1,%2,%3}, {%4,%5,%6,%7}, {%8,%9}, {%0,%1,%2,%3};"               \
        : "+f"((c)[0]), "+f"((c)[1]), "+f"((c)[2]), "+f"((c)[3])              \
        : "r"((a)[0]), "r"((a)[1]), "r"((a)[2]), "r"((a)[3]), "r"(b0), "r"(b1))

// ---------------------------------------------------------------------------
// Kernel 1: warp-per-row L2 norm (clamp 1e-8), write e4m3 of xn * ALPHA * 32
// ---------------------------------------------------------------------------
__global__ void __launch_bounds__(256) norm_kernel(const float* __restrict__ x) {
    int warp = threadIdx.x >> 5, lane = threadIdx.x & 31;
    int row = blockIdx.x * 8 + warp;
    const float4* xr = reinterpret_cast<const float4*>(x + (size_t)row * D);
    float4 v[4];
    float ss = 0.0f;
    #pragma unroll
    for (int i = 0; i < 4; i++) {
        v[i] = xr[lane + 32 * i];
        ss += v[i].x * v[i].x + v[i].y * v[i].y + v[i].z * v[i].z + v[i].w * v[i].w;
    }
    #pragma unroll
    for (int o = 16; o; o >>= 1) ss += __shfl_xor_sync(0xffffffffu, ss, o);
    float inv = (ALPHA * QS) / fmaxf(sqrtf(ss), 1e-8f);
    uint32_t* orow = reinterpret_cast<uint32_t*>(g_xq + (size_t)row * D);
    #pragma unroll
    for (int i = 0; i < 4; i++) {
        uint32_t lo = __nv_cvt_float2_to_fp8x2(make_float2(v[i].x * inv, v[i].y * inv),
                                               __NV_SATFINITE, __NV_E4M3);
        uint32_t hi = __nv_cvt_float2_to_fp8x2(make_float2(v[i].z * inv, v[i].w * inv),
                                               __NV_SATFINITE, __NV_E4M3);
        orow[lane + 32 * i] = lo | (hi << 16);
    }
}

// ---------------------------------------------------------------------------
// Kernel 2: persistent 2-tiles/CTA upper-triangle FP8 MMA + fused epilogue
// 256 thr, warps 4(m)x2(n), warp tile 32x64; BK=128 fp8 (128B rows), 4 chunks,
// 3-stage cp.async, SW128. Grid = 264 CTAs = one residency wave.
// ---------------------------------------------------------------------------
#define TILE_B     16384          // 128 rows x 128B (one matrix, one stage)
#define STAGE_B    32768          // A+B per stage
#define SMEM_TOTAL (1024 + 3 * STAGE_B)

__global__ void __launch_bounds__(256, 2) simexp_mma_kernel() {
    extern __shared__ char smem_raw[];
    uint32_t tiles = (smem_u32(smem_raw) + 1023) & ~1023u;
    float* cs_smem = reinterpret_cast<float*>(smem_raw) +
                     ((tiles - smem_u32(smem_raw)) >> 2);

    const int tid = threadIdx.x, wid = tid >> 5, lane = tid & 31;
    const int wr = wid & 3, wc = wid >> 2;

    // ldmatrix lane mapping (tile-independent; byte math identical to bf16 version)
    const int lr8   = lane & 7;
    const int rin16 = lr8 + ((lane >> 3) & 1) * 8;
    const int hioff = ((lane >> 4) & 1) * 16;
    const uint32_t rx = (uint32_t)lr8 << 4;
    const uint32_t offA0 = (uint32_t)(wr * 32 + rin16) * 128;
    const uint32_t offB0 = (uint32_t)(wc * 64 + rin16) * 128;

    // loader geometry: thread covers rows rb+32p, 16B at byte-col klo
    const int rb = tid >> 3;
    const int klo = (tid & 7) * 16;
    uint32_t swo[4];
    #pragma unroll
    for (int p = 0; p < 4; p++) {
        int row = rb + 32 * p;
        swo[p] = (uint32_t)row * 128 + ((uint32_t)klo ^ ((uint32_t)(row & 7) << 4));
    }

    #pragma unroll 1
    for (int half = 0; half < 2; half++) {
        int b = blockIdx.x * 2 + half, ti = 0;
        while (b >= NTILE - ti) { b -= NTILE - ti; ti++; }
        const int tj = ti + b;
        const int i0 = ti * 128, j0 = tj * 128;
        const bool diag = (ti == tj);
        const uint32_t sBoff = diag ? 0u : (uint32_t)TILE_B;

        const uint8_t *pA[4], *pB[4];
        #pragma unroll
        for (int p = 0; p < 4; p++) {
            int row = rb + 32 * p;
            pA[p] = g_xq + (size_t)(i0 + row) * D + klo;
            pB[p] = g_xq + (size_t)(j0 + row) * D + klo;
        }
        auto load_chunk = [&](int c, int s) {
            uint32_t bA = tiles + (uint32_t)s * STAGE_B;
            #pragma unroll
            for (int p = 0; p < 4; p++) CP16(bA + swo[p], pA[p] + c * 128);
            if (!diag) {
                uint32_t bB = bA + TILE_B;
                #pragma unroll
                for (int p = 0; p < 4; p++) CP16(bB + swo[p], pB[p] + c * 128);
            }
            CP_COMMIT();
        };

        float acc[2][8][4];
        #pragma unroll
        for (int mf = 0; mf < 2; mf++)
            #pragma unroll
            for (int nf = 0; nf < 8; nf++)
                #pragma unroll
                for (int e = 0; e < 4; e++) acc[mf][nf][e] = 0.0f;

        load_chunk(0, 0);
        load_chunk(1, 1);

        for (int c = 0; c < 4; c++) {
            if (c < 3) CP_WAIT1(); else CP_WAIT0();
            __syncthreads();
            if (c + 2 < 4) load_chunk(c + 2, (c + 2) % 3);

            uint32_t sA = tiles + (uint32_t)(c % 3) * STAGE_B;
            uint32_t sB = sA + sBoff;
            #pragma unroll
            for (int ks = 0; ks < 4; ks++) {            // 4 x k32 (32B) per 128B chunk
                uint32_t kx = ((uint32_t)(ks * 32) + hioff) ^ rx;
                uint32_t a[2][4], bb[4][4];
                #pragma unroll
                for (int mf = 0; mf < 2; mf++)
                    LDSM_X4(a[mf][0], a[mf][1], a[mf][2], a[mf][3],
                            sA + offA0 + (uint32_t)mf * 2048 + kx);
                #pragma unroll
                for (int p = 0; p < 4; p++)
                    LDSM_X4(bb[p][0], bb[p][1], bb[p][2], bb[p][3],
                            sB + offB0 + (uint32_t)p * 2048 + kx);
                #pragma unroll
                for (int mf = 0; mf < 2; mf++)
                    #pragma unroll
                    for (int nf = 0; nf < 8; nf++) {
                        int p = nf >> 1, h = nf & 1;
                        MMAFP8(acc[mf][nf], a[mf], bb[p][h], bb[p][h + 2]);
                    }
            }
        }
        __syncthreads();   // mainloop smem dead; cs_smem reuse safe

        // positive logit: tiles with tj-ti == 16 hold (i, i+2048) at local (r, r)
        if (tj - ti == 16) {
            #pragma unroll
            for (int mf = 0; mf < 2; mf++)
                #pragma unroll
                for (int h = 0; h < 2; h++) {
                    int gi = i0 + wr * 32 + mf * 16 + (lane >> 2) + h * 8;
                    int pj = gi + HALF_N;
                    #pragma unroll
                    for (int nf = 0; nf < 8; nf++) {
                        int cb = j0 + wc * 64 + nf * 8 + (lane & 3) * 2;
                        if (cb == pj) {
                            float v = acc[mf][nf][2 * h] * LN2S;
                            g_pos[gi] = v; g_pos[pj & (N2 - 1)] = v;
                        }
                        if (cb + 1 == pj) {
                            float v = acc[mf][nf][2 * h + 1] * LN2S;
                            g_pos[gi] = v; g_pos[pj & (N2 - 1)] = v;
                        }
                    }
                }
        }

        // exp (with 1/1024 rescale) in place
        #pragma unroll
        for (int mf = 0; mf < 2; mf++)
            #pragma unroll
            for (int nf = 0; nf < 8; nf++)
                #pragma unroll
                for (int e = 0; e < 4; e++) acc[mf][nf][e] = ex2f(acc[mf][nf][e] * SCI);

        // row sums -> direct slots
        #pragma unroll
        for (int mf = 0; mf < 2; mf++)
            #pragma unroll
            for (int h = 0; h < 2; h++) {
                float rs = 0.0f;
                #pragma unroll
                for (int nf = 0; nf < 8; nf++)
                    rs += acc[mf][nf][2 * h] + acc[mf][nf][2 * h + 1];
                rs += __shfl_xor_sync(0xffffffffu, rs, 1);
                rs += __shfl_xor_sync(0xffffffffu, rs, 2);
                if ((lane & 3) == 0) {
                    int gi = i0 + wr * 32 + mf * 16 + (lane >> 2) + h * 8;
                    g_part[(size_t)gi * NPART + tj * 2 + wc] = rs;
                }
            }

        // col sums -> transposed slots (off-diagonal tiles only)
        if (!diag) {
            float cs[8][2];
            #pragma unroll
            for (int nf = 0; nf < 8; nf++) {
                cs[nf][0] = acc[0][nf][0] + acc[0][nf][2] + acc[1][nf][0] + acc[1][nf][2];
                cs[nf][1] = acc[0][nf][1] + acc[0][nf][3] + acc[1][nf][1] + acc[1][nf][3];
                #pragma unroll
                for (int o = 4; o <= 16; o <<= 1) {
                    cs[nf][0] += __shfl_xor_sync(0xffffffffu, cs[nf][0], o);
                    cs[nf][1] += __shfl_xor_sync(0xffffffffu, cs[nf][1], o);
                }
            }
            if (lane < 4) {
                #pragma unroll
                for (int nf = 0; nf < 8; nf++) {
                    cs_smem[wr * 128 + wc * 64 + nf * 8 + lane * 2]     = cs[nf][0];
                    cs_smem[wr * 128 + wc * 64 + nf * 8 + lane * 2 + 1] = cs[nf][1];
                }
            }
            __syncthreads();
            if (tid < 128) {
                float t = cs_smem[tid] + cs_smem[128 + tid] +
                          cs_smem[256 + tid] + cs_smem[384 + tid];
                g_part[(size_t)(j0 + tid) * NPART + 64 + ti] = t;
            }
        }
        __syncthreads();   // protect cs_smem/stages before next tile's loads
    }
}

// ---------------------------------------------------------------------------
// Kernel 3: per-row lse - pos, block partials; last block reduces + writes mean
// ---------------------------------------------------------------------------
__global__ void __launch_bounds__(256) finalize_kernel(float* __restrict__ out) {
    const float E2 = 7.38905609893065f;   // exp(sim_ii) = e^2
    int t = threadIdx.x;
    int r = blockIdx.x * 256 + t;
    const float4* pr = reinterpret_cast<const float4*>(g_part + (size_t)r * NPART);
    float s = 0.0f;
    #pragma unroll
    for (int i = 0; i < NPART / 4; i++) {
        float4 v = pr[i];
        s += (v.x + v.y) + (v.z + v.w);
    }
    double d = (double)(logf(s - E2) - g_pos[r]);
    #pragma unroll
    for (int o = 16; o; o >>= 1) d += __shfl_xor_sync(0xffffffffu, d, o);
    __shared__ double ws[8];
    __shared__ int last;
    if ((t & 31) == 0) ws[t >> 5] = d;
    __syncthreads();
    if (t < 8) {
        double u = ws[t];
        #pragma unroll
        for (int o = 4; o; o >>= 1) u += __shfl_xor_sync(0xffu, u, o);
        if (t == 0) {
            g_blk[blockIdx.x] = u;
            __threadfence();
            last = (atomicAdd(&g_cnt, 1) == 15);
        }
    }
    __syncthreads();
    if (last && t < 32) {
        double u = (t < 16) ? g_blk[t] : 0.0;
        #pragma unroll
        for (int o = 16; o; o >>= 1) u += __shfl_xor_sync(0xffffffffu, u, o);
        if (t == 0) { out[0] = (float)(u / (double)N2); g_cnt = 0; }
    }
}

// ---------------------------------------------------------------------------
extern "C" void kernel_launch(void* const* d_in, const int* in_sizes, int n_in,
                              void* d_out, int out_size) {
    const float* x = (const float*)d_in[0];
    float* out = (float*)d_out;

    cudaFuncSetAttribute(simexp_mma_kernel,
                         cudaFuncAttributeMaxDynamicSharedMemorySize, SMEM_TOTAL);

    norm_kernel<<<N2 / 8, 256>>>(x);
    simexp_mma_kernel<<<NBLK / 2, 256, SMEM_TOTAL>>>();
    finalize_kernel<<<16, 256>>>(out);
}